// round 12
// baseline (speedup 1.0000x reference)
#include <cuda_runtime.h>
#include <cuda_fp16.h>

#define N_NODES 10000
#define N_EDGES 160000
#define BATCH   2
#define CIN     16
#define CHID    32
#define TT      8
#define NCLASS  23
#define KW      (N_NODES - NCLASS + 1)   // 9978
#define CHROW   256
#define CAP     64
#define EPS     1e-5f

#define NBLK    148
#define NTHR    1024
#define NTOT    (NBLK * NTHR)            // 151552
#define NWRP    (NBLK * (NTHR / 32))     // 4736

typedef unsigned long long ull;

// ---------------- scratch ----------------
__device__ __half g_xt[N_NODES * CHROW];
__device__ float  g_s[N_NODES * 16];
__device__ int    g_cur[N_NODES];             // reset in phase C each call
__device__ int    g_colpad[N_NODES * CAP];
__device__ float  g_v[BATCH * N_NODES];
__device__ float  g_z[BATCH * N_NODES];
__device__ float  g_stats[17];                // zeroed in phase A each call
// grid barrier state (self-resetting)
__device__ unsigned g_bar_count = 0;
__device__ volatile unsigned g_bar_gen = 0;

// ---------------- f32x2 helpers ----------------
__device__ __forceinline__ ull pack2(float lo, float hi) {
    ull r; asm("mov.b64 %0, {%1, %2};" : "=l"(r) : "f"(lo), "f"(hi)); return r;
}
__device__ __forceinline__ void unpack2(ull v, float& lo, float& hi) {
    asm("mov.b64 {%0, %1}, %2;" : "=f"(lo), "=f"(hi) : "l"(v));
}
__device__ __forceinline__ ull fma2(ull a, ull b, ull c) {
    ull d; asm("fma.rn.f32x2 %0, %1, %2, %3;" : "=l"(d) : "l"(a), "l"(b), "l"(c)); return d;
}

// ---------------- grid barrier (all NBLK blocks co-resident by construction) ----
__device__ __forceinline__ void grid_barrier() {
    __syncthreads();
    if (threadIdx.x == 0) {
        __threadfence();
        unsigned gen = g_bar_gen;
        if (atomicAdd(&g_bar_count, 1u) == NBLK - 1) {
            g_bar_count = 0;
            __threadfence();
            g_bar_gen = gen + 1;
        } else {
            while (g_bar_gen == gen) { __nanosleep(64); }
            __threadfence();
        }
    }
    __syncthreads();
}

// ---------------- the single persistent kernel ----------------
__global__ void __launch_bounds__(NTHR, 1) k_all(
        const float* __restrict__ feat,
        const int* __restrict__ src, const int* __restrict__ dst,
        const float* __restrict__ W1, const float* __restrict__ b1,
        const float* __restrict__ W2, const float* __restrict__ b2,
        const float* __restrict__ tw1, const float* __restrict__ tb1,
        const float* __restrict__ ln1g, const float* __restrict__ ln1b,
        const float* __restrict__ tw2,  const float* __restrict__ tb2,
        const float* __restrict__ ln2g, const float* __restrict__ ln2b,
        const float* __restrict__ fc_w, const float* __restrict__ fc_b,
        float* __restrict__ out) {
    __shared__ float tile[32 * 257];          // 32.9 KB (phase A)
    __shared__ float sW1[CIN * CHID];
    __shared__ float sb1[CHID], sw2[CHID];
    __shared__ float sred[17];
    __shared__ float smom[12];                // {mu1,alpha,mu2,inv2,w2v,bb2} x 2
    __shared__ float red32[32];

    int tid  = threadIdx.x;
    int gtid = blockIdx.x * NTHR + tid;
    int lane = tid & 31;
    int wblk = tid >> 5;

    // ---------------- phase A: weights, stats zero, transpose, bucket build ----
    for (int i = tid; i < CIN * CHID; i += NTHR) sW1[i] = W1[i];
    if (tid < CHID) { sb1[tid] = b1[tid]; sw2[tid] = W2[tid]; }
    if (blockIdx.x == 0 && tid < 17) g_stats[tid] = 0.f;

    for (int t = blockIdx.x; t < 313; t += NBLK) {
        int n0 = t * 32;
        __syncthreads();
        for (int i = tid; i < 8192; i += NTHR) {
            int ch = i >> 5;
            int nn = i & 31;
            int n  = n0 + nn;
            int c  = ch & 15;
            int bt = ch >> 4;
            int tt = bt & 7;
            int b  = bt >> 3;
            float val = 0.f;
            if (n < N_NODES)
                val = feat[(((b * CIN + c) * TT + tt) * N_NODES) + n];
            tile[nn * 257 + ch] = val;
        }
        __syncthreads();
        for (int i = tid; i < 8192; i += NTHR) {
            int r  = i >> 8;
            int ch = i & 255;
            int n  = n0 + r;
            if (n < N_NODES)
                g_xt[n * CHROW + ch] = __float2half(tile[r * 257 + ch]);
        }
    }
    for (int e = gtid; e < N_EDGES; e += NTOT) {
        int d = dst[e];
        int p = atomicAdd(&g_cur[d], 1);
        if (p < CAP) g_colpad[d * CAP + p] = src[e];
    }

    grid_barrier();

    // ---------------- phase B: agg1 (fp16 gather) + MLP (f32x2) ----------------
    {
        int wgid = gtid >> 5;
        int hi = lane & 1;
        const uint4* __restrict__ basep = reinterpret_cast<const uint4*>(g_xt) + lane;
        const uint4* sW4 = reinterpret_cast<const uint4*>(sW1);
        int jb  = hi ? 16 : 0;
        int jb4 = hi ? 4 : 0;
        for (int n = wgid; n < N_NODES; n += NWRP) {
            int cnt = min(g_cur[n], CAP);
            __half2 h0[4], h1[4];
            #pragma unroll
            for (int k = 0; k < 4; k++) { h0[k] = __float2half2_rn(0.f); h1[k] = __float2half2_rn(0.f); }
            const int* __restrict__ colp = g_colpad + n * CAP;
            int e = 0;
            for (; e + 1 < cnt; e += 2) {
                int s0 = colp[e], s1 = colp[e + 1];
                uint4 v0 = basep[s0 * 32];
                uint4 v1 = basep[s1 * 32];
                h0[0] = __hadd2(h0[0], *reinterpret_cast<__half2*>(&v0.x));
                h0[1] = __hadd2(h0[1], *reinterpret_cast<__half2*>(&v0.y));
                h0[2] = __hadd2(h0[2], *reinterpret_cast<__half2*>(&v0.z));
                h0[3] = __hadd2(h0[3], *reinterpret_cast<__half2*>(&v0.w));
                h1[0] = __hadd2(h1[0], *reinterpret_cast<__half2*>(&v1.x));
                h1[1] = __hadd2(h1[1], *reinterpret_cast<__half2*>(&v1.y));
                h1[2] = __hadd2(h1[2], *reinterpret_cast<__half2*>(&v1.z));
                h1[3] = __hadd2(h1[3], *reinterpret_cast<__half2*>(&v1.w));
            }
            if (e < cnt) {
                int s0 = colp[e];
                uint4 v0 = basep[s0 * 32];
                h0[0] = __hadd2(h0[0], *reinterpret_cast<__half2*>(&v0.x));
                h0[1] = __hadd2(h0[1], *reinterpret_cast<__half2*>(&v0.y));
                h0[2] = __hadd2(h0[2], *reinterpret_cast<__half2*>(&v0.z));
                h0[3] = __hadd2(h0[3], *reinterpret_cast<__half2*>(&v0.w));
            }
            float a[8];
            #pragma unroll
            for (int k = 0; k < 4; k++) {
                float2 f0 = __half22float2(h0[k]);
                float2 f1 = __half22float2(h1[k]);
                a[2 * k]     = f0.x + f1.x;
                a[2 * k + 1] = f0.y + f1.y;
            }
            float x[16];
            #pragma unroll
            for (int i = 0; i < 8; i++) {
                float other = __shfl_xor_sync(0xffffffffu, a[i], 1);
                x[i]     = hi ? other : a[i];
                x[8 + i] = hi ? a[i]  : other;
            }
            ull acc2[8];
            #pragma unroll
            for (int k = 0; k < 8; k++) acc2[k] = pack2(sb1[jb + 2 * k], sb1[jb + 2 * k + 1]);
            #pragma unroll
            for (int c = 0; c < 16; c++) {
                ull xc2 = pack2(x[c], x[c]);
                uint4 wa = sW4[c * 8 + jb4 + 0];
                uint4 wb = sW4[c * 8 + jb4 + 1];
                uint4 wc = sW4[c * 8 + jb4 + 2];
                uint4 wd = sW4[c * 8 + jb4 + 3];
                const ull* pa = reinterpret_cast<const ull*>(&wa);
                const ull* pb = reinterpret_cast<const ull*>(&wb);
                const ull* pc = reinterpret_cast<const ull*>(&wc);
                const ull* pd = reinterpret_cast<const ull*>(&wd);
                acc2[0] = fma2(xc2, pa[0], acc2[0]);
                acc2[1] = fma2(xc2, pa[1], acc2[1]);
                acc2[2] = fma2(xc2, pb[0], acc2[2]);
                acc2[3] = fma2(xc2, pb[1], acc2[3]);
                acc2[4] = fma2(xc2, pc[0], acc2[4]);
                acc2[5] = fma2(xc2, pc[1], acc2[5]);
                acc2[6] = fma2(xc2, pd[0], acc2[6]);
                acc2[7] = fma2(xc2, pd[1], acc2[7]);
            }
            float partial = 0.f;
            #pragma unroll
            for (int k = 0; k < 8; k++) {
                float lo, hv;
                unpack2(acc2[k], lo, hv);
                partial = fmaf(fmaxf(lo, 0.f), sw2[jb + 2 * k],     partial);
                partial = fmaf(fmaxf(hv, 0.f), sw2[jb + 2 * k + 1], partial);
            }
            partial += __shfl_xor_sync(0xffffffffu, partial, 1);
            if (!hi) g_s[n * 16 + (lane >> 1)] = partial;
        }
    }

    grid_barrier();

    // ---------------- phase C: agg2 + tconv1 + moment stats + g_cur reset ------
    if (tid < 17) sred[tid] = 0.f;
    __syncthreads();
    {
        float bb  = b2[0];
        float tb  = tb1[0];
        float w2v = tw2[0], bbv = tb2[0];
        for (int gt = gtid; gt < N_NODES * 16; gt += NTOT) {
            int n = gt >> 4;
            int l = gt & 15;
            int cnt = min(g_cur[n], CAP);
            __syncwarp();
            if (l == 0) g_cur[n] = 0;
            const int* __restrict__ colp = g_colpad + n * CAP;
            const float* __restrict__ sp = g_s + l;
            float a0 = 0.f, a1 = 0.f, a2 = 0.f, a3 = 0.f;
            int e = 0;
            for (; e + 4 <= cnt; e += 4) {
                int c0 = colp[e], c1 = colp[e + 1], c2 = colp[e + 2], c3 = colp[e + 3];
                a0 += sp[c0 * 16];
                a1 += sp[c1 * 16];
                a2 += sp[c2 * 16];
                a3 += sp[c3 * 16];
            }
            for (; e < cnt; e++) a0 += sp[colp[e] * 16];
            float acc = (a0 + a1) + (a2 + a3);
            int b = l >> 3;
            int t = l & 7;
            float val = (acc + bb) * tw1[t];
            val += __shfl_down_sync(0xffffffffu, val, 4);
            val += __shfl_down_sync(0xffffffffu, val, 2);
            val += __shfl_down_sync(0xffffffffu, val, 1);
            if (t == 0) {
                float v = val + tb;
                g_v[b * N_NODES + n] = v;
                float g = ln1g[n];
                float q = w2v * ln1b[n] + bbv;
                float u = v * g;
                int o = b * 6;
                atomicAdd(&sred[o + 0], v);
                atomicAdd(&sred[o + 1], v * v);
                atomicAdd(&sred[o + 2], u);
                atomicAdd(&sred[o + 3], u * u);
                atomicAdd(&sred[o + 4], u * g);
                atomicAdd(&sred[o + 5], u * q);
                if (b == 0) {
                    atomicAdd(&sred[12], g);
                    atomicAdd(&sred[13], g * g);
                    atomicAdd(&sred[14], q);
                    atomicAdd(&sred[15], q * q);
                    atomicAdd(&sred[16], g * q);
                }
            }
        }
    }
    __syncthreads();
    if (tid < 17) atomicAdd(&g_stats[tid], sred[tid]);

    grid_barrier();

    // ---------------- phase D1: closed-form moments + z -> global --------------
    if (tid < 2) {
        int b = tid;
        const float invN = 1.f / N_NODES;
        float S1 = g_stats[b * 6 + 0], S2 = g_stats[b * 6 + 1];
        float T1 = g_stats[b * 6 + 2], T2 = g_stats[b * 6 + 3];
        float T3 = g_stats[b * 6 + 4], T4 = g_stats[b * 6 + 5];
        float C1 = g_stats[12], C2 = g_stats[13];
        float Cq = g_stats[14], Cq2 = g_stats[15], Cgq = g_stats[16];
        float w2v = tw2[0], bb2 = tb2[0];
        float mu1  = S1 * invN;
        float var1 = S2 * invN - mu1 * mu1;
        float inv1 = rsqrtf(var1 + EPS);
        float alpha = w2v * inv1;
        float Sy  = alpha * (T1 - mu1 * C1) + Cq;
        float mu2 = Sy * invN;
        float Sy2 = alpha * alpha * (T2 - 2.f * mu1 * T3 + mu1 * mu1 * C2)
                  + 2.f * alpha * (T4 - mu1 * Cgq) + Cq2;
        float var2 = Sy2 * invN - mu2 * mu2;
        float inv2 = rsqrtf(var2 + EPS);
        smom[b * 6 + 0] = mu1;
        smom[b * 6 + 1] = alpha;
        smom[b * 6 + 2] = mu2;
        smom[b * 6 + 3] = inv2;
        smom[b * 6 + 4] = w2v;
        smom[b * 6 + 5] = bb2;
    }
    __syncthreads();
    if (gtid < BATCH * N_NODES) {
        int i = gtid;
        int b = (i >= N_NODES) ? 1 : 0;
        int n = i - b * N_NODES;
        float mu1 = smom[b * 6 + 0], alpha = smom[b * 6 + 1];
        float mu2 = smom[b * 6 + 2], inv2  = smom[b * 6 + 3];
        float w2v = smom[b * 6 + 4], bb2   = smom[b * 6 + 5];
        float v  = g_v[i];
        float y2 = alpha * ln1g[n] * (v - mu1) + fmaf(w2v, ln1b[n], bb2);
        g_z[i]   = (y2 - mu2) * inv2 * ln2g[n] + ln2b[n];
    }

    grid_barrier();

    // ---------------- phase D2: fc conv (blocks 0..45) -------------------------
    if (blockIdx.x < NCLASS * BATCH) {
        int c = blockIdx.x % NCLASS;
        int b = blockIdx.x / NCLASS;
        const float* __restrict__ z = g_z + b * N_NODES + c;
        float a0 = 0.f, a1 = 0.f, a2 = 0.f, a3 = 0.f;
        for (int k0 = tid; k0 < KW; k0 += 4096) {
            int k1 = k0 + 1024, k2 = k0 + 2048, k3 = k0 + 3072;
            bool m1 = k1 < KW, m2 = k2 < KW, m3 = k3 < KW;
            float z0 = z[k0],            w0 = fc_w[k0];
            float z1 = m1 ? z[k1] : 0.f, w1 = m1 ? fc_w[k1] : 0.f;
            float z2 = m2 ? z[k2] : 0.f, w2 = m2 ? fc_w[k2] : 0.f;
            float z3 = m3 ? z[k3] : 0.f, w3 = m3 ? fc_w[k3] : 0.f;
            a0 = fmaf(z0, w0, a0);
            a1 = fmaf(z1, w1, a1);
            a2 = fmaf(z2, w2, a2);
            a3 = fmaf(z3, w3, a3);
        }
        float acc = (a0 + a1) + (a2 + a3);
        acc += __shfl_down_sync(0xffffffffu, acc, 16);
        acc += __shfl_down_sync(0xffffffffu, acc, 8);
        acc += __shfl_down_sync(0xffffffffu, acc, 4);
        acc += __shfl_down_sync(0xffffffffu, acc, 2);
        acc += __shfl_down_sync(0xffffffffu, acc, 1);
        if (lane == 0) red32[wblk] = acc;
        __syncthreads();
        if (tid == 0) {
            float a = 0.f;
            #pragma unroll
            for (int i = 0; i < 32; i++) a += red32[i];
            out[b * NCLASS + c] = a + fc_b[0];
        }
    }
}

// ---------------- launch ----------------
extern "C" void kernel_launch(void* const* d_in, const int* in_sizes, int n_in,
                              void* d_out, int out_size) {
    const float* features = (const float*)d_in[0];
    const int*   src      = (const int*)d_in[1];
    const int*   dst      = (const int*)d_in[2];
    const float* W1       = (const float*)d_in[3];
    const float* b1       = (const float*)d_in[4];
    const float* W2       = (const float*)d_in[5];
    const float* b2       = (const float*)d_in[6];
    const float* tconv1_w = (const float*)d_in[7];
    const float* tconv1_b = (const float*)d_in[8];
    const float* ln1_g    = (const float*)d_in[9];
    const float* ln1_b    = (const float*)d_in[10];
    const float* tconv2_w = (const float*)d_in[11];
    const float* tconv2_b = (const float*)d_in[12];
    const float* ln2_g    = (const float*)d_in[13];
    const float* ln2_b    = (const float*)d_in[14];
    const float* fc_w     = (const float*)d_in[15];
    const float* fc_b     = (const float*)d_in[16];
    float* out = (float*)d_out;

    k_all<<<NBLK, NTHR>>>(features, src, dst, W1, b1, W2, b2,
                          tconv1_w, tconv1_b, ln1_g, ln1_b,
                          tconv2_w, tconv2_b, ln2_g, ln2_b,
                          fc_w, fc_b, out);
}

// round 13
// speedup vs baseline: 1.4383x; 1.4383x over previous
#include <cuda_runtime.h>
#include <cuda_fp16.h>

#define N_NODES 10000
#define N_EDGES 160000
#define BATCH   2
#define CIN     16
#define CHID    32
#define TT      8
#define NCLASS  23
#define KW      (N_NODES - NCLASS + 1)   // 9978
#define CHROW   256
#define CAP     64
#define EPS     1e-5f

typedef unsigned long long ull;

// ---------------- scratch ----------------
__device__ __half g_xt[N_NODES * CHROW];
__device__ float  g_s[N_NODES * 16];
__device__ __align__(16) int   g_cur[N_NODES];      // reset by k_z each call
__device__ int    g_colpad[N_NODES * CAP];
__device__ __align__(16) float g_v[BATCH * N_NODES];
__device__ __align__(16) float g_z[BATCH * N_NODES];
// [b*6+0]=Σv [1]=Σv² [2]=Σvg [3]=Σv²g² [4]=Σvg² [5]=Σvgq ; [12..16]=Σg,Σg²,Σq,Σq²,Σgq
__device__ float  g_stats[17];                      // reset by k_pre each call

// ---------------- f32x2 helpers ----------------
__device__ __forceinline__ ull pack2(float lo, float hi) {
    ull r; asm("mov.b64 %0, {%1, %2};" : "=l"(r) : "f"(lo), "f"(hi)); return r;
}
__device__ __forceinline__ void unpack2(ull v, float& lo, float& hi) {
    asm("mov.b64 {%0, %1}, %2;" : "=f"(lo), "=f"(hi) : "l"(v));
}
__device__ __forceinline__ ull fma2(ull a, ull b, ull c) {
    ull d; asm("fma.rn.f32x2 %0, %1, %2, %3;" : "=l"(d) : "l"(a), "l"(b), "l"(c)); return d;
}

// ---------------- transpose + padded-bucket adjacency build ----------------
__global__ void k_pre(const float* __restrict__ feat,
                      const int* __restrict__ src, const int* __restrict__ dst) {
    if (blockIdx.x < 313) {
        __shared__ float tile[32 * 257];
        int n0 = blockIdx.x * 32;
        int tid = threadIdx.x;   // 256
        #pragma unroll 4
        for (int k = 0; k < 32; k++) {
            int i  = tid + k * 256;
            int ch = i >> 5;
            int nn = i & 31;
            int n  = n0 + nn;
            int c  = ch & 15;
            int bt = ch >> 4;
            int t  = bt & 7;
            int b  = bt >> 3;
            float val = 0.f;
            if (n < N_NODES)
                val = feat[(((b * CIN + c) * TT + t) * N_NODES) + n];
            tile[nn * 257 + ch] = val;
        }
        __syncthreads();
        for (int r = 0; r < 32; r++) {
            int n = n0 + r;
            if (n < N_NODES)
                g_xt[n * CHROW + tid] = __float2half(tile[r * 257 + tid]);
        }
    } else {
        if (blockIdx.x == 313 && threadIdx.x < 17) g_stats[threadIdx.x] = 0.f;
        int base = (blockIdx.x - 313) * 2048 + threadIdx.x;
        #pragma unroll
        for (int k = 0; k < 8; k++) {
            int e = base + k * 256;
            if (e < N_EDGES) {
                int d = dst[e];
                int p = atomicAdd(&g_cur[d], 1);
                if (p < CAP) g_colpad[d * CAP + p] = src[e];
            }
        }
    }
}

// ---------------- fused agg1 (fp16, unroll-2) + MLP (f32x2) ----------------
__global__ void __launch_bounds__(256, 5) k_aggmlp(const float* __restrict__ W1,
                                                   const float* __restrict__ b1,
                                                   const float* __restrict__ W2) {
    __shared__ float sW1[CIN * CHID];
    __shared__ float sb1[CHID], sw2[CHID];
    int tid = threadIdx.x;
    #pragma unroll
    for (int i = tid; i < CIN * CHID; i += 256) sW1[i] = W1[i];
    if (tid < CHID) { sb1[tid] = b1[tid]; sw2[tid] = W2[tid]; }
    __syncthreads();

    cudaGridDependencySynchronize();   // k_pre's g_xt / g_cur / g_colpad

    int gt = blockIdx.x * 256 + tid;     // 1250*256 = N*32 exact
    int n = gt >> 5;
    int lane = gt & 31;
    int cnt = min(g_cur[n], CAP);

    __half2 h0[4], h1[4];
    #pragma unroll
    for (int k = 0; k < 4; k++) { h0[k] = __float2half2_rn(0.f); h1[k] = __float2half2_rn(0.f); }

    const uint4* __restrict__ basep = reinterpret_cast<const uint4*>(g_xt) + lane;
    const int* __restrict__ colp = g_colpad + n * CAP;
    int e = 0;
    for (; e + 1 < cnt; e += 2) {
        int s0 = colp[e], s1 = colp[e + 1];
        uint4 v0 = basep[s0 * 32];
        uint4 v1 = basep[s1 * 32];
        h0[0] = __hadd2(h0[0], *reinterpret_cast<__half2*>(&v0.x));
        h0[1] = __hadd2(h0[1], *reinterpret_cast<__half2*>(&v0.y));
        h0[2] = __hadd2(h0[2], *reinterpret_cast<__half2*>(&v0.z));
        h0[3] = __hadd2(h0[3], *reinterpret_cast<__half2*>(&v0.w));
        h1[0] = __hadd2(h1[0], *reinterpret_cast<__half2*>(&v1.x));
        h1[1] = __hadd2(h1[1], *reinterpret_cast<__half2*>(&v1.y));
        h1[2] = __hadd2(h1[2], *reinterpret_cast<__half2*>(&v1.z));
        h1[3] = __hadd2(h1[3], *reinterpret_cast<__half2*>(&v1.w));
    }
    if (e < cnt) {
        int s0 = colp[e];
        uint4 v0 = basep[s0 * 32];
        h0[0] = __hadd2(h0[0], *reinterpret_cast<__half2*>(&v0.x));
        h0[1] = __hadd2(h0[1], *reinterpret_cast<__half2*>(&v0.y));
        h0[2] = __hadd2(h0[2], *reinterpret_cast<__half2*>(&v0.z));
        h0[3] = __hadd2(h0[3], *reinterpret_cast<__half2*>(&v0.w));
    }

    float a[8];
    #pragma unroll
    for (int k = 0; k < 4; k++) {
        float2 f0 = __half22float2(h0[k]);
        float2 f1 = __half22float2(h1[k]);
        a[2 * k]     = f0.x + f1.x;
        a[2 * k + 1] = f0.y + f1.y;
    }

    int hi = lane & 1;
    float x[16];
    #pragma unroll
    for (int i = 0; i < 8; i++) {
        float other = __shfl_xor_sync(0xffffffffu, a[i], 1);
        x[i]     = hi ? other : a[i];
        x[8 + i] = hi ? a[i]  : other;
    }

    const uint4* sW4 = reinterpret_cast<const uint4*>(sW1);
    int jb  = hi ? 16 : 0;
    int jb4 = hi ? 4 : 0;
    ull acc2[8];
    #pragma unroll
    for (int k = 0; k < 8; k++) acc2[k] = pack2(sb1[jb + 2 * k], sb1[jb + 2 * k + 1]);
    #pragma unroll
    for (int c = 0; c < 16; c++) {
        ull xc2 = pack2(x[c], x[c]);
        uint4 wa = sW4[c * 8 + jb4 + 0];
        uint4 wb = sW4[c * 8 + jb4 + 1];
        uint4 wc = sW4[c * 8 + jb4 + 2];
        uint4 wd = sW4[c * 8 + jb4 + 3];
        const ull* pa = reinterpret_cast<const ull*>(&wa);
        const ull* pb = reinterpret_cast<const ull*>(&wb);
        const ull* pc = reinterpret_cast<const ull*>(&wc);
        const ull* pd = reinterpret_cast<const ull*>(&wd);
        acc2[0] = fma2(xc2, pa[0], acc2[0]);
        acc2[1] = fma2(xc2, pa[1], acc2[1]);
        acc2[2] = fma2(xc2, pb[0], acc2[2]);
        acc2[3] = fma2(xc2, pb[1], acc2[3]);
        acc2[4] = fma2(xc2, pc[0], acc2[4]);
        acc2[5] = fma2(xc2, pc[1], acc2[5]);
        acc2[6] = fma2(xc2, pd[0], acc2[6]);
        acc2[7] = fma2(xc2, pd[1], acc2[7]);
    }
    float partial = 0.f;
    #pragma unroll
    for (int k = 0; k < 8; k++) {
        float lo, hv;
        unpack2(acc2[k], lo, hv);
        partial = fmaf(fmaxf(lo, 0.f), sw2[jb + 2 * k],     partial);
        partial = fmaf(fmaxf(hv, 0.f), sw2[jb + 2 * k + 1], partial);
    }
    partial += __shfl_xor_sync(0xffffffffu, partial, 1);
    if (!hi) g_s[n * 16 + (lane >> 1)] = partial;
}

// agg2 + b2 + tconv1 -> g_v[b][n]; accumulates LN statistics
__global__ void __launch_bounds__(128, 8) k_agg2(const float* __restrict__ b2,
                                                 const float* __restrict__ tw1,
                                                 const float* __restrict__ tb1,
                                                 const float* __restrict__ ln1g,
                                                 const float* __restrict__ ln1b,
                                                 const float* __restrict__ tw2,
                                                 const float* __restrict__ tb2) {
    __shared__ float sred[17];
    int tid = threadIdx.x;
    if (tid < 17) sred[tid] = 0.f;
    __syncthreads();

    cudaGridDependencySynchronize();   // k_aggmlp's g_s

    int gt = blockIdx.x * blockDim.x + tid;  // 1250*128 = N*16
    int n = gt >> 4;
    int l = gt & 15;
    int cnt = min(g_cur[n], CAP);
    const int* __restrict__ colp = g_colpad + n * CAP;
    const float* __restrict__ sp = g_s + l;
    float a0 = 0.f, a1 = 0.f, a2 = 0.f, a3 = 0.f;
    int e = 0;
    for (; e + 4 <= cnt; e += 4) {
        int c0 = colp[e], c1 = colp[e + 1], c2 = colp[e + 2], c3 = colp[e + 3];
        a0 += sp[c0 * 16];
        a1 += sp[c1 * 16];
        a2 += sp[c2 * 16];
        a3 += sp[c3 * 16];
    }
    for (; e < cnt; e++) a0 += sp[colp[e] * 16];
    float acc = (a0 + a1) + (a2 + a3);
    int b = l >> 3;
    int t = l & 7;
    float val = (acc + b2[0]) * tw1[t];
    val += __shfl_down_sync(0xffffffffu, val, 4);
    val += __shfl_down_sync(0xffffffffu, val, 2);
    val += __shfl_down_sync(0xffffffffu, val, 1);
    if (t == 0) {
        float v = val + tb1[0];
        g_v[b * N_NODES + n] = v;
        float g = ln1g[n];
        float q = tw2[0] * ln1b[n] + tb2[0];
        float u = v * g;
        int o = b * 6;
        atomicAdd(&sred[o + 0], v);
        atomicAdd(&sred[o + 1], v * v);
        atomicAdd(&sred[o + 2], u);
        atomicAdd(&sred[o + 3], u * u);
        atomicAdd(&sred[o + 4], u * g);
        atomicAdd(&sred[o + 5], u * q);
        if (b == 0) {
            atomicAdd(&sred[12], g);
            atomicAdd(&sred[13], g * g);
            atomicAdd(&sred[14], q);
            atomicAdd(&sred[15], q * q);
            atomicAdd(&sred[16], g * q);
        }
    }
    __syncthreads();
    if (tid < 17) atomicAdd(&g_stats[tid], sred[tid]);
}

// z from closed-form LN moments, fully float4-vectorized; resets g_cur
__global__ void __launch_bounds__(256) k_z(
        const float* __restrict__ ln1g, const float* __restrict__ ln1b,
        const float* __restrict__ tw2,  const float* __restrict__ tb2,
        const float* __restrict__ ln2g, const float* __restrict__ ln2b) {
    cudaGridDependencySynchronize();  // k_agg2's g_stats / g_v

    int t = blockIdx.x * 256 + threadIdx.x;   // 20 blocks: 5120 threads
    if (t < N_NODES / 4) reinterpret_cast<int4*>(g_cur)[t] = make_int4(0, 0, 0, 0);
    const int Q = N_NODES / 4;                // 2500 float4 per batch
    if (t >= BATCH * Q) return;
    int b  = (t >= Q) ? 1 : 0;
    int n4 = t - b * Q;                       // float4 index within batch

    const float invN = 1.f / N_NODES;
    float S1 = g_stats[b * 6 + 0], S2 = g_stats[b * 6 + 1];
    float T1 = g_stats[b * 6 + 2], T2 = g_stats[b * 6 + 3];
    float T3 = g_stats[b * 6 + 4], T4 = g_stats[b * 6 + 5];
    float C1 = g_stats[12], C2 = g_stats[13];
    float Cq = g_stats[14], Cq2 = g_stats[15], Cgq = g_stats[16];
    float w2v = tw2[0], bb2 = tb2[0];

    float mu1  = S1 * invN;
    float var1 = S2 * invN - mu1 * mu1;
    float inv1 = rsqrtf(var1 + EPS);
    float alpha = w2v * inv1;
    float Sy  = alpha * (T1 - mu1 * C1) + Cq;
    float mu2 = Sy * invN;
    float Sy2 = alpha * alpha * (T2 - 2.f * mu1 * T3 + mu1 * mu1 * C2)
              + 2.f * alpha * (T4 - mu1 * Cgq) + Cq2;
    float var2 = Sy2 * invN - mu2 * mu2;
    float inv2 = rsqrtf(var2 + EPS);

    float4 v  = reinterpret_cast<const float4*>(g_v + b * N_NODES)[n4];
    float4 g1 = reinterpret_cast<const float4*>(ln1g)[n4];
    float4 p1 = reinterpret_cast<const float4*>(ln1b)[n4];
    float4 g2 = reinterpret_cast<const float4*>(ln2g)[n4];
    float4 p2 = reinterpret_cast<const float4*>(ln2b)[n4];

    float4 z;
    {
        float y;
        y = alpha * g1.x * (v.x - mu1) + fmaf(w2v, p1.x, bb2);
        z.x = (y - mu2) * inv2 * g2.x + p2.x;
        y = alpha * g1.y * (v.y - mu1) + fmaf(w2v, p1.y, bb2);
        z.y = (y - mu2) * inv2 * g2.y + p2.y;
        y = alpha * g1.z * (v.z - mu1) + fmaf(w2v, p1.z, bb2);
        z.z = (y - mu2) * inv2 * g2.z + p2.z;
        y = alpha * g1.w * (v.w - mu1) + fmaf(w2v, p1.w, bb2);
        z.w = (y - mu2) * inv2 * g2.w + p2.w;
    }
    reinterpret_cast<float4*>(g_z + b * N_NODES)[n4] = z;
}

// fc conv: 8-deep pipelined dot, 512 threads, one block per (class, batch)
__global__ void __launch_bounds__(512) k_fc(const float* __restrict__ fc_w,
                                            const float* __restrict__ fc_b,
                                            float* __restrict__ out) {
    __shared__ float red32[32];
    cudaGridDependencySynchronize();  // k_z's g_z

    int c = blockIdx.x, b = blockIdx.y;
    int tid = threadIdx.x;
    const float* __restrict__ z = g_z + b * N_NODES + c;
    float a0=0.f,a1=0.f,a2=0.f,a3=0.f,a4=0.f,a5=0.f,a6=0.f,a7=0.f;
    for (int k0 = tid; k0 < KW; k0 += 4096) {
        int k1 = k0 + 512,  k2 = k0 + 1024, k3 = k0 + 1536;
        int k4 = k0 + 2048, k5 = k0 + 2560, k6 = k0 + 3072, k7 = k0 + 3584;
        float z0 = z[k0],                     w0 = fc_w[k0];
        float z1 = (k1 < KW) ? z[k1] : 0.f,   w1 = (k1 < KW) ? fc_w[k1] : 0.f;
        float z2 = (k2 < KW) ? z[k2] : 0.f,   w2 = (k2 < KW) ? fc_w[k2] : 0.f;
        float z3 = (k3 < KW) ? z[k3] : 0.f,   w3 = (k3 < KW) ? fc_w[k3] : 0.f;
        float z4 = (k4 < KW) ? z[k4] : 0.f,   w4 = (k4 < KW) ? fc_w[k4] : 0.f;
        float z5 = (k5 < KW) ? z[k5] : 0.f,   w5 = (k5 < KW) ? fc_w[k5] : 0.f;
        float z6 = (k6 < KW) ? z[k6] : 0.f,   w6 = (k6 < KW) ? fc_w[k6] : 0.f;
        float z7 = (k7 < KW) ? z[k7] : 0.f,   w7 = (k7 < KW) ? fc_w[k7] : 0.f;
        a0 = fmaf(z0, w0, a0); a1 = fmaf(z1, w1, a1);
        a2 = fmaf(z2, w2, a2); a3 = fmaf(z3, w3, a3);
        a4 = fmaf(z4, w4, a4); a5 = fmaf(z5, w5, a5);
        a6 = fmaf(z6, w6, a6); a7 = fmaf(z7, w7, a7);
    }
    float acc = ((a0 + a1) + (a2 + a3)) + ((a4 + a5) + (a6 + a7));
    int lane = tid & 31, w = tid >> 5;
    acc += __shfl_down_sync(0xffffffffu, acc, 16);
    acc += __shfl_down_sync(0xffffffffu, acc, 8);
    acc += __shfl_down_sync(0xffffffffu, acc, 4);
    acc += __shfl_down_sync(0xffffffffu, acc, 2);
    acc += __shfl_down_sync(0xffffffffu, acc, 1);
    if (lane == 0) red32[w] = acc;
    __syncthreads();
    if (tid == 0) {
        float a = 0.f;
        #pragma unroll
        for (int i = 0; i < 16; i++) a += red32[i];
        out[b * NCLASS + c] = a + fc_b[0];
    }
}

// ---------------- PDL launch helper ----------------
template <typename F, typename... Args>
static void launch_pdl(F func, dim3 grid, dim3 block, Args... args) {
    cudaLaunchConfig_t cfg = {};
    cfg.gridDim = grid;
    cfg.blockDim = block;
    cfg.dynamicSmemBytes = 0;
    cfg.stream = 0;
    cudaLaunchAttribute attr[1];
    attr[0].id = cudaLaunchAttributeProgrammaticStreamSerialization;
    attr[0].val.programmaticStreamSerializationAllowed = 1;
    cfg.attrs = attr;
    cfg.numAttrs = 1;
    cudaLaunchKernelEx(&cfg, func, args...);
}

// ---------------- launch ----------------
extern "C" void kernel_launch(void* const* d_in, const int* in_sizes, int n_in,
                              void* d_out, int out_size) {
    const float* features = (const float*)d_in[0];
    const int*   src      = (const int*)d_in[1];
    const int*   dst      = (const int*)d_in[2];
    const float* W1       = (const float*)d_in[3];
    const float* b1       = (const float*)d_in[4];
    const float* W2       = (const float*)d_in[5];
    const float* b2       = (const float*)d_in[6];
    const float* tconv1_w = (const float*)d_in[7];
    const float* tconv1_b = (const float*)d_in[8];
    const float* ln1_g    = (const float*)d_in[9];
    const float* ln1_b    = (const float*)d_in[10];
    const float* tconv2_w = (const float*)d_in[11];
    const float* tconv2_b = (const float*)d_in[12];
    const float* ln2_g    = (const float*)d_in[13];
    const float* ln2_b    = (const float*)d_in[14];
    const float* fc_w     = (const float*)d_in[15];
    const float* fc_b     = (const float*)d_in[16];
    float* out = (float*)d_out;

    k_pre<<<392, 256>>>(features, src, dst);
    launch_pdl(k_aggmlp, dim3(1250), dim3(256), W1, b1, W2);
    launch_pdl(k_agg2, dim3(1250), dim3(128), b2, tconv1_w, tconv1_b,
               ln1_g, ln1_b, tconv2_w, tconv2_b);
    launch_pdl(k_z, dim3(20), dim3(256), ln1_g, ln1_b, tconv2_w, tconv2_b,
               ln2_g, ln2_b);
    launch_pdl(k_fc, dim3(NCLASS, BATCH), dim3(512), fc_w, fc_b, out);
}

// round 14
// speedup vs baseline: 1.4432x; 1.0034x over previous
#include <cuda_runtime.h>
#include <cuda_fp16.h>

#define N_NODES 10000
#define N_EDGES 160000
#define BATCH   2
#define CIN     16
#define CHID    32
#define TT      8
#define NCLASS  23
#define KW      (N_NODES - NCLASS + 1)   // 9978
#define CHROW   256
#define CAP     64
#define EPS     1e-5f

typedef unsigned long long ull;

// ---------------- scratch ----------------
__device__ __half g_xt[N_NODES * CHROW];
__device__ float  g_s[N_NODES * 16];
__device__ __align__(16) int   g_cur[N_NODES];      // reset by k_agg2 each call
__device__ int    g_colpad[N_NODES * CAP];
__device__ __align__(16) float g_v[BATCH * N_NODES];
__device__ float  g_w2a[NCLASS * KW];               // w[k]*g1[c+k]*g2[c+k]
__device__ float  g_csum[NCLASS * 4];               // S_A, S_B, S_C, S_D per class
// [b*6+0]=Σv [1]=Σv² [2]=Σvg [3]=Σv²g² [4]=Σvg² [5]=Σvgq ; [12..16]=Σg,Σg²,Σq,Σq²,Σgq
__device__ float  g_stats[17];                      // reset by k_pre each call

// ---------------- f32x2 helpers ----------------
__device__ __forceinline__ ull pack2(float lo, float hi) {
    ull r; asm("mov.b64 %0, {%1, %2};" : "=l"(r) : "f"(lo), "f"(hi)); return r;
}
__device__ __forceinline__ void unpack2(ull v, float& lo, float& hi) {
    asm("mov.b64 {%0, %1}, %2;" : "=f"(lo), "=f"(hi) : "l"(v));
}
__device__ __forceinline__ ull fma2(ull a, ull b, ull c) {
    ull d; asm("fma.rn.f32x2 %0, %1, %2, %3;" : "=l"(d) : "l"(a), "l"(b), "l"(c)); return d;
}

// ---------------- transpose + bucket build + fc-weight prep ----------------
// blocks [0,313): transpose. [313,392): edge buckets. [392,415): W2A + const sums.
__global__ void k_pre(const float* __restrict__ feat,
                      const int* __restrict__ src, const int* __restrict__ dst,
                      const float* __restrict__ ln1g, const float* __restrict__ ln1b,
                      const float* __restrict__ tw2,  const float* __restrict__ tb2,
                      const float* __restrict__ ln2g, const float* __restrict__ ln2b,
                      const float* __restrict__ fc_w) {
    if (blockIdx.x < 313) {
        __shared__ float tile[32 * 257];
        int n0 = blockIdx.x * 32;
        int tid = threadIdx.x;   // 256
        #pragma unroll 4
        for (int k = 0; k < 32; k++) {
            int i  = tid + k * 256;
            int ch = i >> 5;
            int nn = i & 31;
            int n  = n0 + nn;
            int c  = ch & 15;
            int bt = ch >> 4;
            int t  = bt & 7;
            int b  = bt >> 3;
            float val = 0.f;
            if (n < N_NODES)
                val = feat[(((b * CIN + c) * TT + t) * N_NODES) + n];
            tile[nn * 257 + ch] = val;
        }
        __syncthreads();
        for (int r = 0; r < 32; r++) {
            int n = n0 + r;
            if (n < N_NODES)
                g_xt[n * CHROW + tid] = __float2half(tile[r * 257 + tid]);
        }
    } else if (blockIdx.x < 392) {
        if (blockIdx.x == 313 && threadIdx.x < 17) g_stats[threadIdx.x] = 0.f;
        int base = (blockIdx.x - 313) * 2048 + threadIdx.x;
        #pragma unroll
        for (int k = 0; k < 8; k++) {
            int e = base + k * 256;
            if (e < N_EDGES) {
                int d = dst[e];
                int p = atomicAdd(&g_cur[d], 1);
                if (p < CAP) g_colpad[d * CAP + p] = src[e];
            }
        }
    } else {
        // W2A prep: block c computes W2A[c][k] = w[k]*g1[c+k]*g2[c+k]
        // and S_A = Σ w*A, S_B = Σ w*(g2*(w2*p1+bb2)), S_C = Σ w*g2, S_D = Σ w*p2
        __shared__ float red[4][8];
        int c = blockIdx.x - 392;
        int tid = threadIdx.x;   // 256
        float w2v = tw2[0], bb2 = tb2[0];
        float sA = 0.f, sB = 0.f, sC = 0.f, sD = 0.f;
        for (int k = tid; k < KW; k += 256) {
            int i = c + k;
            float w  = fc_w[k];
            float a  = ln1g[i] * ln2g[i];
            float bq = ln2g[i] * fmaf(w2v, ln1b[i], bb2);
            float wa = w * a;
            g_w2a[c * KW + k] = wa;
            sA += wa;
            sB = fmaf(w, bq, sB);
            sC = fmaf(w, ln2g[i], sC);
            sD = fmaf(w, ln1b[i] * 0.f + ln2b[i], sD);
        }
        int lane = tid & 31, wrp = tid >> 5;
        #pragma unroll
        for (int off = 16; off > 0; off >>= 1) {
            sA += __shfl_down_sync(0xffffffffu, sA, off);
            sB += __shfl_down_sync(0xffffffffu, sB, off);
            sC += __shfl_down_sync(0xffffffffu, sC, off);
            sD += __shfl_down_sync(0xffffffffu, sD, off);
        }
        if (lane == 0) { red[0][wrp] = sA; red[1][wrp] = sB; red[2][wrp] = sC; red[3][wrp] = sD; }
        __syncthreads();
        if (tid < 4) {
            float s = 0.f;
            #pragma unroll
            for (int i = 0; i < 8; i++) s += red[tid][i];
            g_csum[c * 4 + tid] = s;
        }
    }
}

// ---------------- fused agg1 (fp16, unroll-2) + MLP (f32x2) ----------------
__global__ void __launch_bounds__(256, 5) k_aggmlp(const float* __restrict__ W1,
                                                   const float* __restrict__ b1,
                                                   const float* __restrict__ W2) {
    __shared__ float sW1[CIN * CHID];
    __shared__ float sb1[CHID], sw2[CHID];
    int tid = threadIdx.x;
    #pragma unroll
    for (int i = tid; i < CIN * CHID; i += 256) sW1[i] = W1[i];
    if (tid < CHID) { sb1[tid] = b1[tid]; sw2[tid] = W2[tid]; }
    __syncthreads();

    cudaGridDependencySynchronize();   // k_pre's g_xt / g_cur / g_colpad

    int gt = blockIdx.x * 256 + tid;     // 1250*256 = N*32 exact
    int n = gt >> 5;
    int lane = gt & 31;
    int cnt = min(g_cur[n], CAP);

    __half2 h0[4], h1[4];
    #pragma unroll
    for (int k = 0; k < 4; k++) { h0[k] = __float2half2_rn(0.f); h1[k] = __float2half2_rn(0.f); }

    const uint4* __restrict__ basep = reinterpret_cast<const uint4*>(g_xt) + lane;
    const int* __restrict__ colp = g_colpad + n * CAP;
    int e = 0;
    for (; e + 1 < cnt; e += 2) {
        int s0 = colp[e], s1 = colp[e + 1];
        uint4 v0 = basep[s0 * 32];
        uint4 v1 = basep[s1 * 32];
        h0[0] = __hadd2(h0[0], *reinterpret_cast<__half2*>(&v0.x));
        h0[1] = __hadd2(h0[1], *reinterpret_cast<__half2*>(&v0.y));
        h0[2] = __hadd2(h0[2], *reinterpret_cast<__half2*>(&v0.z));
        h0[3] = __hadd2(h0[3], *reinterpret_cast<__half2*>(&v0.w));
        h1[0] = __hadd2(h1[0], *reinterpret_cast<__half2*>(&v1.x));
        h1[1] = __hadd2(h1[1], *reinterpret_cast<__half2*>(&v1.y));
        h1[2] = __hadd2(h1[2], *reinterpret_cast<__half2*>(&v1.z));
        h1[3] = __hadd2(h1[3], *reinterpret_cast<__half2*>(&v1.w));
    }
    if (e < cnt) {
        int s0 = colp[e];
        uint4 v0 = basep[s0 * 32];
        h0[0] = __hadd2(h0[0], *reinterpret_cast<__half2*>(&v0.x));
        h0[1] = __hadd2(h0[1], *reinterpret_cast<__half2*>(&v0.y));
        h0[2] = __hadd2(h0[2], *reinterpret_cast<__half2*>(&v0.z));
        h0[3] = __hadd2(h0[3], *reinterpret_cast<__half2*>(&v0.w));
    }

    float a[8];
    #pragma unroll
    for (int k = 0; k < 4; k++) {
        float2 f0 = __half22float2(h0[k]);
        float2 f1 = __half22float2(h1[k]);
        a[2 * k]     = f0.x + f1.x;
        a[2 * k + 1] = f0.y + f1.y;
    }

    int hi = lane & 1;
    float x[16];
    #pragma unroll
    for (int i = 0; i < 8; i++) {
        float other = __shfl_xor_sync(0xffffffffu, a[i], 1);
        x[i]     = hi ? other : a[i];
        x[8 + i] = hi ? a[i]  : other;
    }

    const uint4* sW4 = reinterpret_cast<const uint4*>(sW1);
    int jb  = hi ? 16 : 0;
    int jb4 = hi ? 4 : 0;
    ull acc2[8];
    #pragma unroll
    for (int k = 0; k < 8; k++) acc2[k] = pack2(sb1[jb + 2 * k], sb1[jb + 2 * k + 1]);
    #pragma unroll
    for (int c = 0; c < 16; c++) {
        ull xc2 = pack2(x[c], x[c]);
        uint4 wa = sW4[c * 8 + jb4 + 0];
        uint4 wb = sW4[c * 8 + jb4 + 1];
        uint4 wc = sW4[c * 8 + jb4 + 2];
        uint4 wd = sW4[c * 8 + jb4 + 3];
        const ull* pa = reinterpret_cast<const ull*>(&wa);
        const ull* pb = reinterpret_cast<const ull*>(&wb);
        const ull* pc = reinterpret_cast<const ull*>(&wc);
        const ull* pd = reinterpret_cast<const ull*>(&wd);
        acc2[0] = fma2(xc2, pa[0], acc2[0]);
        acc2[1] = fma2(xc2, pa[1], acc2[1]);
        acc2[2] = fma2(xc2, pb[0], acc2[2]);
        acc2[3] = fma2(xc2, pb[1], acc2[3]);
        acc2[4] = fma2(xc2, pc[0], acc2[4]);
        acc2[5] = fma2(xc2, pc[1], acc2[5]);
        acc2[6] = fma2(xc2, pd[0], acc2[6]);
        acc2[7] = fma2(xc2, pd[1], acc2[7]);
    }
    float partial = 0.f;
    #pragma unroll
    for (int k = 0; k < 8; k++) {
        float lo, hv;
        unpack2(acc2[k], lo, hv);
        partial = fmaf(fmaxf(lo, 0.f), sw2[jb + 2 * k],     partial);
        partial = fmaf(fmaxf(hv, 0.f), sw2[jb + 2 * k + 1], partial);
    }
    partial += __shfl_xor_sync(0xffffffffu, partial, 1);
    if (!hi) g_s[n * 16 + (lane >> 1)] = partial;
}

// agg2 + b2 + tconv1 -> g_v[b][n]; accumulates LN stats; resets g_cur
__global__ void __launch_bounds__(128, 8) k_agg2(const float* __restrict__ b2,
                                                 const float* __restrict__ tw1,
                                                 const float* __restrict__ tb1,
                                                 const float* __restrict__ ln1g,
                                                 const float* __restrict__ ln1b,
                                                 const float* __restrict__ tw2,
                                                 const float* __restrict__ tb2) {
    __shared__ float sred[17];
    int tid = threadIdx.x;
    if (tid < 17) sred[tid] = 0.f;
    __syncthreads();

    cudaGridDependencySynchronize();   // k_aggmlp's g_s

    int gt = blockIdx.x * blockDim.x + tid;  // 1250*128 = N*16, each n once
    int n = gt >> 4;
    int l = gt & 15;
    int cnt = min(g_cur[n], CAP);
    __syncwarp();
    if (l == 0) g_cur[n] = 0;                // reset for next replay
    const int* __restrict__ colp = g_colpad + n * CAP;
    const float* __restrict__ sp = g_s + l;
    float a0 = 0.f, a1 = 0.f, a2 = 0.f, a3 = 0.f;
    int e = 0;
    for (; e + 4 <= cnt; e += 4) {
        int c0 = colp[e], c1 = colp[e + 1], c2 = colp[e + 2], c3 = colp[e + 3];
        a0 += sp[c0 * 16];
        a1 += sp[c1 * 16];
        a2 += sp[c2 * 16];
        a3 += sp[c3 * 16];
    }
    for (; e < cnt; e++) a0 += sp[colp[e] * 16];
    float acc = (a0 + a1) + (a2 + a3);
    int b = l >> 3;
    int t = l & 7;
    float val = (acc + b2[0]) * tw1[t];
    val += __shfl_down_sync(0xffffffffu, val, 4);
    val += __shfl_down_sync(0xffffffffu, val, 2);
    val += __shfl_down_sync(0xffffffffu, val, 1);
    if (t == 0) {
        float v = val + tb1[0];
        g_v[b * N_NODES + n] = v;
        float g = ln1g[n];
        float q = tw2[0] * ln1b[n] + tb2[0];
        float u = v * g;
        int o = b * 6;
        atomicAdd(&sred[o + 0], v);
        atomicAdd(&sred[o + 1], v * v);
        atomicAdd(&sred[o + 2], u);
        atomicAdd(&sred[o + 3], u * u);
        atomicAdd(&sred[o + 4], u * g);
        atomicAdd(&sred[o + 5], u * q);
        if (b == 0) {
            atomicAdd(&sred[12], g);
            atomicAdd(&sred[13], g * g);
            atomicAdd(&sred[14], q);
            atomicAdd(&sred[15], q * q);
            atomicAdd(&sred[16], g * q);
        }
    }
    __syncthreads();
    if (tid < 17) atomicAdd(&g_stats[tid], sred[tid]);
}

// fc conv on v directly: out = k1*dot(W2A[c], v[c:]) + linear(csum) + fc_b
__global__ void __launch_bounds__(512) k_fc(const float* __restrict__ tw2,
                                            const float* __restrict__ tb2,
                                            const float* __restrict__ fc_b,
                                            float* __restrict__ out) {
    __shared__ float red32[32];
    cudaGridDependencySynchronize();  // k_agg2's g_stats / g_v

    int c = blockIdx.x, b = blockIdx.y;
    int tid = threadIdx.x;

    // moments -> k1..k4
    const float invN = 1.f / N_NODES;
    float S1 = g_stats[b * 6 + 0], S2 = g_stats[b * 6 + 1];
    float T1 = g_stats[b * 6 + 2], T2 = g_stats[b * 6 + 3];
    float T3 = g_stats[b * 6 + 4], T4 = g_stats[b * 6 + 5];
    float C1 = g_stats[12], C2 = g_stats[13];
    float Cq = g_stats[14], Cq2 = g_stats[15], Cgq = g_stats[16];
    float w2v = tw2[0], bb2 = tb2[0];
    float mu1  = S1 * invN;
    float var1 = S2 * invN - mu1 * mu1;
    float inv1 = rsqrtf(var1 + EPS);
    float alpha = w2v * inv1;
    float Sy  = alpha * (T1 - mu1 * C1) + Cq;
    float mu2 = Sy * invN;
    float Sy2 = alpha * alpha * (T2 - 2.f * mu1 * T3 + mu1 * mu1 * C2)
              + 2.f * alpha * (T4 - mu1 * Cgq) + Cq2;
    float var2 = Sy2 * invN - mu2 * mu2;
    float inv2 = rsqrtf(var2 + EPS);
    float k1 = alpha * inv2;
    float k2 = -alpha * mu1 * inv2;
    float k3 = inv2;
    float k4 = -mu2 * inv2;

    const float* __restrict__ v  = g_v + b * N_NODES + c;
    const float* __restrict__ wa = g_w2a + c * KW;
    float a0=0.f,a1=0.f,a2=0.f,a3=0.f,a4=0.f,a5=0.f,a6=0.f,a7=0.f;
    for (int k0 = tid; k0 < KW; k0 += 4096) {
        int kk1 = k0 + 512,  kk2 = k0 + 1024, kk3 = k0 + 1536;
        int kk4 = k0 + 2048, kk5 = k0 + 2560, kk6 = k0 + 3072, kk7 = k0 + 3584;
        float z0 = v[k0],                        w0 = wa[k0];
        float z1 = (kk1 < KW) ? v[kk1] : 0.f,    w1 = (kk1 < KW) ? wa[kk1] : 0.f;
        float z2 = (kk2 < KW) ? v[kk2] : 0.f,    w2 = (kk2 < KW) ? wa[kk2] : 0.f;
        float z3 = (kk3 < KW) ? v[kk3] : 0.f,    w3 = (kk3 < KW) ? wa[kk3] : 0.f;
        float z4 = (kk4 < KW) ? v[kk4] : 0.f,    w4 = (kk4 < KW) ? wa[kk4] : 0.f;
        float z5 = (kk5 < KW) ? v[kk5] : 0.f,    w5 = (kk5 < KW) ? wa[kk5] : 0.f;
        float z6 = (kk6 < KW) ? v[kk6] : 0.f,    w6 = (kk6 < KW) ? wa[kk6] : 0.f;
        float z7 = (kk7 < KW) ? v[kk7] : 0.f,    w7 = (kk7 < KW) ? wa[kk7] : 0.f;
        a0 = fmaf(z0, w0, a0); a1 = fmaf(z1, w1, a1);
        a2 = fmaf(z2, w2, a2); a3 = fmaf(z3, w3, a3);
        a4 = fmaf(z4, w4, a4); a5 = fmaf(z5, w5, a5);
        a6 = fmaf(z6, w6, a6); a7 = fmaf(z7, w7, a7);
    }
    float acc = ((a0 + a1) + (a2 + a3)) + ((a4 + a5) + (a6 + a7));
    int lane = tid & 31, w = tid >> 5;
    acc += __shfl_down_sync(0xffffffffu, acc, 16);
    acc += __shfl_down_sync(0xffffffffu, acc, 8);
    acc += __shfl_down_sync(0xffffffffu, acc, 4);
    acc += __shfl_down_sync(0xffffffffu, acc, 2);
    acc += __shfl_down_sync(0xffffffffu, acc, 1);
    if (lane == 0) red32[w] = acc;
    __syncthreads();
    if (tid == 0) {
        float dot = 0.f;
        #pragma unroll
        for (int i = 0; i < 16; i++) dot += red32[i];
        float r = k1 * dot
                + k2 * g_csum[c * 4 + 0]
                + k3 * g_csum[c * 4 + 1]
                + k4 * g_csum[c * 4 + 2]
                +      g_csum[c * 4 + 3];
        out[b * NCLASS + c] = r + fc_b[0];
    }
}

// ---------------- PDL launch helper ----------------
template <typename F, typename... Args>
static void launch_pdl(F func, dim3 grid, dim3 block, Args... args) {
    cudaLaunchConfig_t cfg = {};
    cfg.gridDim = grid;
    cfg.blockDim = block;
    cfg.dynamicSmemBytes = 0;
    cfg.stream = 0;
    cudaLaunchAttribute attr[1];
    attr[0].id = cudaLaunchAttributeProgrammaticStreamSerialization;
    attr[0].val.programmaticStreamSerializationAllowed = 1;
    cfg.attrs = attr;
    cfg.numAttrs = 1;
    cudaLaunchKernelEx(&cfg, func, args...);
}

// ---------------- launch ----------------
extern "C" void kernel_launch(void* const* d_in, const int* in_sizes, int n_in,
                              void* d_out, int out_size) {
    const float* features = (const float*)d_in[0];
    const int*   src      = (const int*)d_in[1];
    const int*   dst      = (const int*)d_in[2];
    const float* W1       = (const float*)d_in[3];
    const float* b1       = (const float*)d_in[4];
    const float* W2       = (const float*)d_in[5];
    const float* b2       = (const float*)d_in[6];
    const float* tconv1_w = (const float*)d_in[7];
    const float* tconv1_b = (const float*)d_in[8];
    const float* ln1_g    = (const float*)d_in[9];
    const float* ln1_b    = (const float*)d_in[10];
    const float* tconv2_w = (const float*)d_in[11];
    const float* tconv2_b = (const float*)d_in[12];
    const float* ln2_g    = (const float*)d_in[13];
    const float* ln2_b    = (const float*)d_in[14];
    const float* fc_w     = (const float*)d_in[15];
    const float* fc_b     = (const float*)d_in[16];
    float* out = (float*)d_out;

    k_pre<<<415, 256>>>(features, src, dst, ln1_g, ln1_b, tconv2_w, tconv2_b,
                        ln2_g, ln2_b, fc_w);
    launch_pdl(k_aggmlp, dim3(1250), dim3(256), W1, b1, W2);
    launch_pdl(k_agg2, dim3(1250), dim3(128), b2, tconv1_w, tconv1_b,
               ln1_g, ln1_b, tconv2_w, tconv2_b);
    launch_pdl(k_fc, dim3(NCLASS, BATCH), dim3(512), tconv2_w, tconv2_b, fc_b, out);
}